// round 11
// baseline (speedup 1.0000x reference)
#include <cuda_runtime.h>

// MN neuron scan: T=1000 steps, B*N = 32768 independent neurons.
//
// R8: packed f32x2 arithmetic (Blackwell FFMA2 path).
//  - 4 neurons/thread as 2 packed f32x2 pairs: halves instruction count vs
//    scalar (we are warp-issue-bound: IPC 0.46, pipes <30%), and gives each
//    of the 256 warps its own SMSP with 2 independent dependency chains.
//  - add/mul/fma.rn.f32x2 are per-lane IEEE rn ops -> the validated
//    XLA-uncontracted, bit-exact op ordering is preserved per neuron.
//    Subtraction a-b is computed as add(a, mul(x,-k)) where the negated
//    product is exact (-rn(p) == rn(-p)).
//  - LDG.128/STG.128 per step; ping-pong float4 prefetch, 10-step distance
//    (~1100 cyc > ~1050-cyc NAT DRAM latency).

#define T_STEPS 1000
#define NN      512
#define BN      32768          // B * N
#define NT      (BN / 4)       // threads (4 neurons each) = 8192
#define UPF     5              // steps per prefetch group (ping-pong x2)

typedef unsigned long long u64;

__device__ __forceinline__ u64 pk2(float lo, float hi) {
    u64 r; asm("mov.b64 %0, {%1, %2};" : "=l"(r) : "f"(lo), "f"(hi)); return r;
}
__device__ __forceinline__ void up2(u64 v, float& lo, float& hi) {
    asm("mov.b64 {%0, %1}, %2;" : "=f"(lo), "=f"(hi) : "l"(v));
}
__device__ __forceinline__ u64 add2(u64 a, u64 b) {
    u64 d; asm("add.rn.f32x2 %0, %1, %2;" : "=l"(d) : "l"(a), "l"(b)); return d;
}
__device__ __forceinline__ u64 mul2(u64 a, u64 b) {
    u64 d; asm("mul.rn.f32x2 %0, %1, %2;" : "=l"(d) : "l"(a), "l"(b)); return d;
}
__device__ __forceinline__ u64 fma2(u64 a, u64 b, u64 c) {
    u64 d; asm("fma.rn.f32x2 %0, %1, %2, %3;" : "=l"(d) : "l"(a), "l"(b), "l"(c)); return d;
}

struct PState { u64 V, i1, i2, Th; };
struct PConst {
    u64 nK1, nK2, DT, NEL, nG, NTIN, nB, NEG1, R1, R2;
};

// One bit-exact step for a packed pair of neurons. Returns packed spikes {0,1}.
__device__ __forceinline__ void step_pair(PState& s, u64 xt,
                                          u64 lw, u64 av, u64 A1v, u64 A2v,
                                          const PConst& C,
                                          float& spx, float& spy)
{
    // i1 = i1 - rn(rn(K1*i1)*DT)   (via exact negation)
    u64 m1 = mul2(s.i1, C.nK1); m1 = mul2(m1, C.DT); s.i1 = add2(s.i1, m1);
    u64 m2 = mul2(s.i2, C.nK2); m2 = mul2(m2, C.DT); s.i2 = add2(s.i2, m2);

    // V += DT * (((lin*xt + i1) + i2) - G*(V-EL))
    u64 lx  = mul2(lw, xt);
    u64 ss  = add2(lx, s.i1);
    ss      = add2(ss, s.i2);
    u64 vel = add2(s.V, C.NEL);       // rn(V - EL)
    u64 gqn = mul2(vel, C.nG);        // -rn(G*(V-EL))
    u64 dv  = add2(ss, gqn);          // rn(s - gq)
    dv      = mul2(dv, C.DT);
    s.V     = add2(s.V, dv);

    // Thr += DT * (a*(V-EL) - B*(Thr-TINF))
    u64 ve2 = add2(s.V, C.NEL);
    u64 t1  = mul2(av, ve2);
    u64 tt  = add2(s.Th, C.NTIN);     // rn(Thr - TINF)
    u64 t2n = mul2(tt, C.nB);         // -rn(B*(Thr-TINF))
    u64 dd  = add2(t1, t2n);
    dd      = mul2(dd, C.DT);
    s.Th    = add2(s.Th, dd);

    // vm = V - Thr
    u64 vm  = fma2(s.Th, C.NEG1, s.V);

    // reset candidates (two-rounded, as reference: rn(rn(R*i)+A))
    u64 i1n = add2(mul2(s.i1, C.R1), A1v);
    u64 i2n = add2(mul2(s.i2, C.R2), A2v);

    // per-lane spike + exact selects
    float vmx, vmy;  up2(vm, vmx, vmy);
    const bool px = (vmx > 0.0f);
    const bool py = (vmy > 0.0f);

    float ax, ay, bx, by;

    up2(s.i1, ax, ay); up2(i1n, bx, by);
    s.i1 = pk2(px ? bx : ax, py ? by : ay);

    up2(s.i2, ax, ay); up2(i2n, bx, by);
    s.i2 = pk2(px ? bx : ax, py ? by : ay);

    up2(s.Th, ax, ay);
    s.Th = pk2(px ? fmaxf(ax, -0.06f) : ax, py ? fmaxf(ay, -0.06f) : ay);

    up2(s.V, ax, ay);
    s.V = pk2(px ? -0.07f : ax, py ? -0.07f : ay);

    spx = px ? 1.0f : 0.0f;
    spy = py ? 1.0f : 0.0f;
}

__global__ __launch_bounds__(32)
void mn_neuron_kernel(const float* __restrict__ x,
                      const float* __restrict__ lin,
                      const float* __restrict__ aarr,
                      const float* __restrict__ A1arr,
                      const float* __restrict__ A2arr,
                      float* __restrict__ out)
{
    const int gid = blockIdx.x * 32 + threadIdx.x;   // quad id in [0, NT)
    const int n0  = (4 * gid) & (NN - 1);            // 4-aligned neuron index

    // Packed constants
    PConst C;
    C.nK1  = pk2(-200.0f, -200.0f);
    C.nK2  = pk2(-20.0f, -20.0f);
    C.DT   = pk2(0.01f, 0.01f);
    C.NEL  = pk2(0.07f, 0.07f);      // -EL
    C.nG   = pk2(-45.24007797241211f, -45.24007797241211f);
    C.NTIN = pk2(0.05f, 0.05f);      // -TINF
    C.nB   = pk2(-12.77495288848877f, -12.77495288848877f);
    C.NEG1 = pk2(-1.0f, -1.0f);
    C.R1   = pk2(0.3858567178249359f, 0.3858567178249359f);
    C.R2   = pk2(-1.1421641111373901f, -1.1421641111373901f);

    // Per-quad parameters (16B-aligned)
    const float4 l4  = *(const float4*)(lin   + n0);
    const float4 a4  = *(const float4*)(aarr  + n0);
    const float4 A14 = *(const float4*)(A1arr + n0);
    const float4 A24 = *(const float4*)(A2arr + n0);
    const u64 lwA = pk2(l4.x,  l4.y),  lwB = pk2(l4.z,  l4.w);
    const u64 avA = pk2(a4.x,  a4.y),  avB = pk2(a4.z,  a4.w);
    const u64 A1A = pk2(A14.x, A14.y), A1B = pk2(A14.z, A14.w);
    const u64 A2A = pk2(A24.x, A24.y), A2B = pk2(A24.z, A24.w);

    PState sA = { pk2(-0.07f, -0.07f), pk2(0.f, 0.f), pk2(0.f, 0.f), pk2(-0.05f, -0.05f) };
    PState sB = sA;

    const float4* xp = (const float4*)x   + gid;   // stride NT per step
    float4*       op = (float4*)      out + gid;

    // Prime two prefetch groups (10 LDG.128 in flight, ~10-step distance)
    float4 bufA[UPF], bufB[UPF];
#pragma unroll
    for (int u = 0; u < UPF; ++u) bufA[u] = xp[(size_t)u * NT];
#pragma unroll
    for (int u = 0; u < UPF; ++u) bufB[u] = xp[(size_t)(UPF + u) * NT];

    for (int t0 = 0; t0 < T_STEPS; t0 += 2 * UPF) {
        float4 cur[UPF];

        // ---- phase A ----
#pragma unroll
        for (int u = 0; u < UPF; ++u) cur[u] = bufA[u];
        if (t0 + 2 * UPF < T_STEPS) {
            const float4* np = xp + (size_t)(t0 + 2 * UPF) * NT;
#pragma unroll
            for (int u = 0; u < UPF; ++u) bufA[u] = np[(size_t)u * NT];
        }
#pragma unroll
        for (int u = 0; u < UPF; ++u) {
            const u64 xA = pk2(cur[u].x, cur[u].y);
            const u64 xB = pk2(cur[u].z, cur[u].w);
            float4 sp;
            step_pair(sA, xA, lwA, avA, A1A, A2A, C, sp.x, sp.y);
            step_pair(sB, xB, lwB, avB, A1B, A2B, C, sp.z, sp.w);
            op[(size_t)(t0 + u) * NT] = sp;
        }

        // ---- phase B ----
#pragma unroll
        for (int u = 0; u < UPF; ++u) cur[u] = bufB[u];
        if (t0 + 3 * UPF < T_STEPS) {
            const float4* np = xp + (size_t)(t0 + 3 * UPF) * NT;
#pragma unroll
            for (int u = 0; u < UPF; ++u) bufB[u] = np[(size_t)u * NT];
        }
#pragma unroll
        for (int u = 0; u < UPF; ++u) {
            const u64 xA = pk2(cur[u].x, cur[u].y);
            const u64 xB = pk2(cur[u].z, cur[u].w);
            float4 sp;
            step_pair(sA, xA, lwA, avA, A1A, A2A, C, sp.x, sp.y);
            step_pair(sB, xB, lwB, avB, A1B, A2B, C, sp.z, sp.w);
            op[(size_t)(t0 + UPF + u) * NT] = sp;
        }
    }
}

extern "C" void kernel_launch(void* const* d_in, const int* in_sizes, int n_in,
                              void* d_out, int out_size)
{
    const float* x   = (const float*)d_in[0];  // [T, B, N]
    const float* lin = (const float*)d_in[1];  // [1, N]
    const float* a   = (const float*)d_in[2];  // [1, N]
    const float* A1  = (const float*)d_in[3];  // [1, N]
    const float* A2  = (const float*)d_in[4];  // [1, N]
    float* out = (float*)d_out;                // [T, B, N]

    (void)in_sizes; (void)n_in; (void)out_size;

    mn_neuron_kernel<<<NT / 32, 32>>>(x, lin, a, A1, A2, out);
}

// round 12
// speedup vs baseline: 1.0383x; 1.0383x over previous
#include <cuda_runtime.h>

// MN neuron scan: T=1000 steps, B*N = 32768 independent neurons.
//
// R11: packed f32x2, 2 neurons/thread (512 warps — the proven-best warp count
// from R7; R8's 4-neurons/thread starved the SMSPs at 0.43 warps/SMSP).
// Packing fuses the two per-neuron dependency chains into ONE packed chain so
// the overlap can't be lost by the ptxas scheduler (R7's two scalar chains
// were serialized: 165 cyc/step for a ~70-cycle ideal).
//  - All arithmetic is add/mul/fma.rn.f32x2 (per-lane IEEE rn; bit-exactness
//    of this exact op ordering validated in R8, rel_err 0.0).
//  - a-b computed as add(a, mul(x,-k)): negation commutes exactly through rn.
//  - 128-thread blocks: 4 warps/block -> one warp per SMSP on 128 SMs.
//  - In-place group double-buffer prefetch: consume buf[u], reload it for
//    group g+2 (~20-step / ~1400-cycle issue-to-use distance > DRAM latency).

#define T_STEPS 1000
#define NN      512
#define BN      32768          // B * N
#define NT2     (BN / 2)       // threads (2 neurons each) = 16384
#define UPF     10             // steps per group
#define NGRP    (T_STEPS / UPF)

typedef unsigned long long u64;

__device__ __forceinline__ u64 pk2(float lo, float hi) {
    u64 r; asm("mov.b64 %0, {%1, %2};" : "=l"(r) : "f"(lo), "f"(hi)); return r;
}
__device__ __forceinline__ void up2(u64 v, float& lo, float& hi) {
    asm("mov.b64 {%0, %1}, %2;" : "=f"(lo), "=f"(hi) : "l"(v));
}
__device__ __forceinline__ u64 add2(u64 a, u64 b) {
    u64 d; asm("add.rn.f32x2 %0, %1, %2;" : "=l"(d) : "l"(a), "l"(b)); return d;
}
__device__ __forceinline__ u64 mul2(u64 a, u64 b) {
    u64 d; asm("mul.rn.f32x2 %0, %1, %2;" : "=l"(d) : "l"(a), "l"(b)); return d;
}
__device__ __forceinline__ u64 fma2(u64 a, u64 b, u64 c) {
    u64 d; asm("fma.rn.f32x2 %0, %1, %2, %3;" : "=l"(d) : "l"(a), "l"(b), "l"(c)); return d;
}

struct PState { u64 V, i1, i2, Th; };
struct PConst { u64 nK1, nK2, DT, NEL, nG, NTIN, nB, NEG1, R1, R2; };

// One bit-exact step for the packed neuron pair; writes packed spikes {0,1}.
__device__ __forceinline__ void step_pair(PState& s, u64 xt,
                                          u64 lw, u64 av, u64 A1v, u64 A2v,
                                          const PConst& C, float2& sp)
{
    // i1 = i1 - rn(rn(K1*i1)*DT); i2 likewise (exact negation form)
    u64 m1 = mul2(s.i1, C.nK1); m1 = mul2(m1, C.DT); s.i1 = add2(s.i1, m1);
    u64 m2 = mul2(s.i2, C.nK2); m2 = mul2(m2, C.DT); s.i2 = add2(s.i2, m2);

    // V += DT * (((lin*xt + i1) + i2) - G*(V-EL))
    u64 lx  = mul2(lw, xt);
    u64 ss  = add2(lx, s.i1);
    ss      = add2(ss, s.i2);
    u64 vel = add2(s.V, C.NEL);     // rn(V - EL)
    u64 gqn = mul2(vel, C.nG);      // -rn(G*(V-EL))
    u64 dv  = add2(ss, gqn);
    dv      = mul2(dv, C.DT);
    s.V     = add2(s.V, dv);

    // Thr += DT * (a*(V-EL) - B*(Thr-TINF))
    u64 ve2 = add2(s.V, C.NEL);
    u64 t1  = mul2(av, ve2);
    u64 tt  = add2(s.Th, C.NTIN);   // rn(Thr - TINF)
    u64 t2n = mul2(tt, C.nB);       // -rn(B*(Thr-TINF))
    u64 dd  = add2(t1, t2n);
    dd      = mul2(dd, C.DT);
    s.Th    = add2(s.Th, dd);

    // spk = (V - Thr) > 0
    u64 vm  = fma2(s.Th, C.NEG1, s.V);

    // reset candidates (two-rounded, as reference)
    u64 i1n = add2(mul2(s.i1, C.R1), A1v);
    u64 i2n = add2(mul2(s.i2, C.R2), A2v);

    float vmx, vmy;  up2(vm, vmx, vmy);
    const bool px = (vmx > 0.0f);
    const bool py = (vmy > 0.0f);

    float ax, ay, bx, by;
    up2(s.i1, ax, ay); up2(i1n, bx, by);
    s.i1 = pk2(px ? bx : ax, py ? by : ay);
    up2(s.i2, ax, ay); up2(i2n, bx, by);
    s.i2 = pk2(px ? bx : ax, py ? by : ay);
    up2(s.Th, ax, ay);
    s.Th = pk2(px ? fmaxf(ax, -0.06f) : ax, py ? fmaxf(ay, -0.06f) : ay);
    up2(s.V, ax, ay);
    s.V = pk2(px ? -0.07f : ax, py ? -0.07f : ay);

    sp.x = px ? 1.0f : 0.0f;
    sp.y = py ? 1.0f : 0.0f;
}

__global__ __launch_bounds__(128)
void mn_neuron_kernel(const float* __restrict__ x,
                      const float* __restrict__ lin,
                      const float* __restrict__ aarr,
                      const float* __restrict__ A1arr,
                      const float* __restrict__ A2arr,
                      float* __restrict__ out)
{
    const int gid = blockIdx.x * 128 + threadIdx.x;  // pair id in [0, NT2)
    const int n0  = (2 * gid) & (NN - 1);            // even neuron index

    PConst C;
    C.nK1  = pk2(-200.0f, -200.0f);
    C.nK2  = pk2(-20.0f, -20.0f);
    C.DT   = pk2(0.01f, 0.01f);
    C.NEL  = pk2(0.07f, 0.07f);      // -EL
    C.nG   = pk2(-45.24007797241211f, -45.24007797241211f);
    C.NTIN = pk2(0.05f, 0.05f);      // -TINF
    C.nB   = pk2(-12.77495288848877f, -12.77495288848877f);
    C.NEG1 = pk2(-1.0f, -1.0f);
    C.R1   = pk2(0.3858567178249359f, 0.3858567178249359f);
    C.R2   = pk2(-1.1421641111373901f, -1.1421641111373901f);

    const float2 l2  = *(const float2*)(lin   + n0);
    const float2 a2  = *(const float2*)(aarr  + n0);
    const float2 A12 = *(const float2*)(A1arr + n0);
    const float2 A22 = *(const float2*)(A2arr + n0);
    const u64 lw  = pk2(l2.x,  l2.y);
    const u64 av  = pk2(a2.x,  a2.y);
    const u64 A1v = pk2(A12.x, A12.y);
    const u64 A2v = pk2(A22.x, A22.y);

    PState s = { pk2(-0.07f, -0.07f), pk2(0.f, 0.f), pk2(0.f, 0.f), pk2(-0.05f, -0.05f) };

    const float2* xp = (const float2*)x   + gid;     // stride NT2 per step
    float2*       op = (float2*)      out + gid;

    // Prime two groups (20 LDG.64 in flight)
    float2 bufA[UPF], bufB[UPF];
#pragma unroll
    for (int u = 0; u < UPF; ++u) bufA[u] = xp[(size_t)u * NT2];
#pragma unroll
    for (int u = 0; u < UPF; ++u) bufB[u] = xp[(size_t)(UPF + u) * NT2];

    for (int g = 0; g < NGRP; g += 2) {
        const bool pfA = (g + 2) < NGRP;
        const bool pfB = (g + 3) < NGRP;
        const float2* npA = xp + (size_t)(g + 2) * UPF * NT2;
        const float2* npB = xp + (size_t)(g + 3) * UPF * NT2;

        // ---- phase A: steps g*UPF .. g*UPF+UPF-1 ----
#pragma unroll
        for (int u = 0; u < UPF; ++u) {
            const float2 xv = bufA[u];
            if (pfA) bufA[u] = npA[(size_t)u * NT2];   // reload slot for g+2
            const u64 xt = pk2(xv.x, xv.y);
            float2 sp;
            step_pair(s, xt, lw, av, A1v, A2v, C, sp);
            op[(size_t)(g * UPF + u) * NT2] = sp;
        }

        // ---- phase B: steps (g+1)*UPF .. ----
#pragma unroll
        for (int u = 0; u < UPF; ++u) {
            const float2 xv = bufB[u];
            if (pfB) bufB[u] = npB[(size_t)u * NT2];   // reload slot for g+3
            const u64 xt = pk2(xv.x, xv.y);
            float2 sp;
            step_pair(s, xt, lw, av, A1v, A2v, C, sp);
            op[(size_t)((g + 1) * UPF + u) * NT2] = sp;
        }
    }
}

extern "C" void kernel_launch(void* const* d_in, const int* in_sizes, int n_in,
                              void* d_out, int out_size)
{
    const float* x   = (const float*)d_in[0];  // [T, B, N]
    const float* lin = (const float*)d_in[1];  // [1, N]
    const float* a   = (const float*)d_in[2];  // [1, N]
    const float* A1  = (const float*)d_in[3];  // [1, N]
    const float* A2  = (const float*)d_in[4];  // [1, N]
    float* out = (float*)d_out;                // [T, B, N]

    (void)in_sizes; (void)n_in; (void)out_size;

    mn_neuron_kernel<<<NT2 / 128, 128>>>(x, lin, a, A1, A2, out);
}

// round 13
// speedup vs baseline: 1.1271x; 1.0855x over previous
#include <cuda_runtime.h>

// MN neuron scan: T=1000 steps, B*N = 32768 independent neurons.
//
// R12: R7's proven scalar ffma arithmetic (bit-exact, rel_err 0.0) with the
// warp-placement and scheduling fixes:
//  - 2 neurons/thread (512 warps), ops of the two neurons explicitly
//    interleaved at source so the independent chains overlap.
//  - 128-thread blocks, 128 CTAs -> 1 CTA/SM, exactly 1 warp per SMSP
//    (B300 maps SMSP = wid%4; R6/R7's 1-warp blocks stacked all warps on
//    SMSP0 -> warps contended for one scheduler).
//  - In-place reload prefetch: one LDG.64 per step, 20-step issue-to-use
//    distance; avoids front-batched load bursts (cross-CTA L1tex-queue
//    spread penalty at high MLP_p1).
// Every op is fma.rn.f32 via inline asm: a+b == fma(a,1,b), a*k == fma(a,k,-0.0)
// -> FFMA-imm (rt 1) while preserving XLA's uncontracted per-op IEEE rounding.

#define T_STEPS 1000
#define NN      512
#define BN      32768          // B * N
#define NT2     (BN / 2)       // threads, 2 neurons each = 16384
#define UPF     10             // steps per prefetch group (ping-pong x2)
#define NGRP    (T_STEPS / UPF)

__device__ __forceinline__ float ffma(float a, float b, float c) {
    float d;
    asm("fma.rn.f32 %0, %1, %2, %3;" : "=f"(d) : "f"(a), "f"(b), "f"(c));
    return d;
}

__global__ __launch_bounds__(128)
void mn_neuron_kernel(const float* __restrict__ x,
                      const float* __restrict__ lin,
                      const float* __restrict__ aarr,
                      const float* __restrict__ A1arr,
                      const float* __restrict__ A2arr,
                      float* __restrict__ out)
{
    const int gid = blockIdx.x * 128 + threadIdx.x;  // pair id in [0, NT2)
    const int n0  = (2 * gid) & (NN - 1);            // even neuron index

    // Constants (exact fp32 of the reference values)
    const float VR   = -0.07f;
    const float TR   = -0.06f;
    const float NEL  =  0.07f;   // -EL
    const float NTIN =  0.05f;   // -TINF
    const float DT   = 0.01f;
    const float K1   = 200.0f;
    const float K2   = 20.0f;
    const float Gc   = 45.24007797241211f;
    const float Bc   = 12.77495288848877f;
    const float R1   = 0.3858567178249359f;
    const float R2   = -1.1421641111373901f;
    const float NZ   = -0.0f;

    // Per-pair parameters (8B-aligned vector loads)
    const float2 l2  = *(const float2*)(lin   + n0);
    const float2 a2  = *(const float2*)(aarr  + n0);
    const float2 A12 = *(const float2*)(A1arr + n0);
    const float2 A22 = *(const float2*)(A2arr + n0);

    // State, two independent neurons (suffix a/b)
    float Va = -0.07f, i1a = 0.0f, i2a = 0.0f, Ta = -0.05f;
    float Vb = -0.07f, i1b = 0.0f, i2b = 0.0f, Tb = -0.05f;

    const float2* xp = (const float2*)x   + gid;     // stride NT2 per step
    float2*       op = (float2*)      out + gid;

    // Prime two prefetch groups (20 LDG.64 outstanding)
    float2 bufA[UPF], bufB[UPF];
#pragma unroll
    for (int u = 0; u < UPF; ++u) bufA[u] = xp[(size_t)u * NT2];
#pragma unroll
    for (int u = 0; u < UPF; ++u) bufB[u] = xp[(size_t)(UPF + u) * NT2];

    for (int g = 0; g < NGRP; g += 2) {
        const bool pfA = (g + 2) < NGRP;
        const bool pfB = (g + 3) < NGRP;
        const float2* npA = xp + (size_t)(g + 2) * UPF * NT2;
        const float2* npB = xp + (size_t)(g + 3) * UPF * NT2;

#pragma unroll
        for (int ph = 0; ph < 2; ++ph) {
#pragma unroll
            for (int u = 0; u < UPF; ++u) {
                // consume slot, immediately reload it for group g+2/g+3
                float2 xv;
                if (ph == 0) { xv = bufA[u]; if (pfA) bufA[u] = npA[(size_t)u * NT2]; }
                else         { xv = bufB[u]; if (pfB) bufB[u] = npB[(size_t)u * NT2]; }

                // ---- one step, both neurons interleaved (bit-exact order per neuron) ----
                // i1 -= (K1*i1)*DT ; i2 -= (K2*i2)*DT
                float m1a = ffma(i1a, K1, NZ);     float m1b = ffma(i1b, K1, NZ);
                float m2a = ffma(i2a, K2, NZ);     float m2b = ffma(i2b, K2, NZ);
                m1a = ffma(m1a, DT, NZ);           m1b = ffma(m1b, DT, NZ);
                m2a = ffma(m2a, DT, NZ);           m2b = ffma(m2b, DT, NZ);
                i1a = ffma(m1a, -1.0f, i1a);       i1b = ffma(m1b, -1.0f, i1b);
                i2a = ffma(m2a, -1.0f, i2a);       i2b = ffma(m2b, -1.0f, i2b);

                // V += DT * (((lin*xt + i1) + i2) - G*(V-EL))
                float lxa = ffma(l2.x, xv.x, NZ);  float lxb = ffma(l2.y, xv.y, NZ);
                float sa  = ffma(lxa, 1.0f, i1a);  float sb  = ffma(lxb, 1.0f, i1b);
                sa        = ffma(sa,  1.0f, i2a);  sb        = ffma(sb,  1.0f, i2b);
                float vea = ffma(Va, 1.0f, NEL);   float veb = ffma(Vb, 1.0f, NEL);
                float gqa = ffma(vea, Gc, NZ);     float gqb = ffma(veb, Gc, NZ);
                float dva = ffma(gqa, -1.0f, sa);  float dvb = ffma(gqb, -1.0f, sb);
                dva       = ffma(dva, DT, NZ);     dvb       = ffma(dvb, DT, NZ);
                Va        = ffma(dva, 1.0f, Va);   Vb        = ffma(dvb, 1.0f, Vb);

                // Thr += DT * (a*(V-EL) - B*(Thr-TINF))
                float v2a = ffma(Va, 1.0f, NEL);   float v2b = ffma(Vb, 1.0f, NEL);
                float t1a = ffma(a2.x, v2a, NZ);   float t1b = ffma(a2.y, v2b, NZ);
                float tta = ffma(Ta, 1.0f, NTIN);  float ttb = ffma(Tb, 1.0f, NTIN);
                float t2a = ffma(tta, Bc, NZ);     float t2b = ffma(ttb, Bc, NZ);
                float dda = ffma(t2a, -1.0f, t1a); float ddb = ffma(t2b, -1.0f, t1b);
                dda       = ffma(dda, DT, NZ);     ddb       = ffma(ddb, DT, NZ);
                Ta        = ffma(dda, 1.0f, Ta);   Tb        = ffma(ddb, 1.0f, Tb);

                // spk = (V - Thr) > 0
                float vma = ffma(Ta, -1.0f, Va);   float vmb = ffma(Tb, -1.0f, Vb);
                const bool pa = (vma > 0.0f);      const bool pb = (vmb > 0.0f);

                // reset candidates (two-rounded as reference), then exact selects
                float na1 = ffma(ffma(i1a, R1, NZ), 1.0f, A12.x);
                float nb1 = ffma(ffma(i1b, R1, NZ), 1.0f, A12.y);
                float na2 = ffma(ffma(i2a, R2, NZ), 1.0f, A22.x);
                float nb2 = ffma(ffma(i2b, R2, NZ), 1.0f, A22.y);
                i1a = pa ? na1 : i1a;              i1b = pb ? nb1 : i1b;
                i2a = pa ? na2 : i2a;              i2b = pb ? nb2 : i2b;
                Ta  = pa ? fmaxf(Ta, TR) : Ta;     Tb  = pb ? fmaxf(Tb, TR) : Tb;
                Va  = pa ? VR : Va;                Vb  = pb ? VR : Vb;

                float2 sp;
                sp.x = pa ? 1.0f : 0.0f;
                sp.y = pb ? 1.0f : 0.0f;
                op[(size_t)((g + ph) * UPF + u) * NT2] = sp;
            }
        }
    }
}

extern "C" void kernel_launch(void* const* d_in, const int* in_sizes, int n_in,
                              void* d_out, int out_size)
{
    const float* x   = (const float*)d_in[0];  // [T, B, N]
    const float* lin = (const float*)d_in[1];  // [1, N]
    const float* a   = (const float*)d_in[2];  // [1, N]
    const float* A1  = (const float*)d_in[3];  // [1, N]
    const float* A2  = (const float*)d_in[4];  // [1, N]
    float* out = (float*)d_out;                // [T, B, N]

    (void)in_sizes; (void)n_in; (void)out_size;

    mn_neuron_kernel<<<NT2 / 128, 128>>>(x, lin, a, A1, A2, out);
}